// round 3
// baseline (speedup 1.0000x reference)
#include <cuda_runtime.h>

#define N_IN        1024
#define N_OUT       4096
#define BATCH       8
#define OC          64
#define THREADS     256
#define M_PER_BLOCK 256

__device__ __forceinline__ float ex2_approx(float x) {
    float r;
    asm("ex2.approx.ftz.f32 %0, %1;" : "=f"(r) : "f"(x));
    return r;
}

__global__ __launch_bounds__(THREADS, 1)
void conv_deepset_kernel(const float* __restrict__ x,
                         const float* __restrict__ y,
                         const float* __restrict__ t,
                         const float* __restrict__ sigma,
                         const float* __restrict__ W,
                         const float* __restrict__ bias,
                         float* __restrict__ out)
{
    __shared__ float4 pts[N_IN];          // (x0, x1, y, pad)
    __shared__ float  dens_s[M_PER_BLOCK];
    __shared__ float  q_s[M_PER_BLOCK];
    __shared__ float  Ws[2 * OC];
    __shared__ float  bs[OC];

    const int b   = blockIdx.y;
    const int tid = threadIdx.x;
    const int m   = blockIdx.x * M_PER_BLOCK + tid;   // tid == m_local

    // ---- stage batch-b context points into smem ----
    const float2* __restrict__ xb = (const float2*)(x + (size_t)b * N_IN * 2);
    const float*  __restrict__ yb = y + (size_t)b * N_IN;
    #pragma unroll
    for (int i = tid; i < N_IN; i += THREADS) {
        float2 xv = xb[i];
        pts[i] = make_float4(xv.x, xv.y, yb[i], 0.0f);
    }
    if (tid < 2 * OC) Ws[tid] = W[tid];
    if (tid < OC)     bs[tid] = bias[tid];
    __syncthreads();

    // ---- per-channel exponent constants: e = exp2( d * c ), c = -0.5*log2e/s^2 ----
    const float LOG2E = 1.4426950408889634f;
    // 1/s^2 = exp(-2*sigma); use accurate expf (runs once per thread)
    const float c0 = -0.5f * LOG2E * expf(-2.0f * sigma[0]);
    const float c1 = -0.5f * LOG2E * expf(-2.0f * sigma[1]);

    const float2 tv = ((const float2*)(t + (size_t)b * N_OUT * 2))[m];
    const float tx = tv.x, ty = tv.y;

    float acc0 = 0.0f;   // density channel (weights = 1)
    float acc1 = 0.0f;   // conv channel    (weights = y)

    if (c0 == c1) {
        // single-MUFU fast path (uniform branch; the common init has equal sigmas)
        #pragma unroll 8
        for (int n = 0; n < N_IN; ++n) {
            float4 p = pts[n];
            float dx = p.x - tx;
            float dy = p.y - ty;
            float d  = fmaf(dy, dy, dx * dx);
            float e0 = ex2_approx(d * c0);
            acc0 += e0;
            acc1 = fmaf(p.z, e0, acc1);
        }
    } else {
        #pragma unroll 8
        for (int n = 0; n < N_IN; ++n) {
            float4 p = pts[n];
            float dx = p.x - tx;
            float dy = p.y - ty;
            float d  = fmaf(dy, dy, dx * dx);
            float e0 = ex2_approx(d * c0);
            float e1 = ex2_approx(d * c1);
            acc0 += e0;
            acc1 = fmaf(p.z, e1, acc1);
        }
    }

    dens_s[tid] = acc0;
    q_s[tid]    = acc1 / (acc0 + 1e-8f);
    __syncthreads();

    // ---- epilogue: out[b, m, o] = dens*W[o,0] + q*W[o,1] + b[o], coalesced float4 stores ----
    float4* __restrict__ ob =
        (float4*)(out + ((size_t)b * N_OUT + (size_t)blockIdx.x * M_PER_BLOCK) * OC);

    #pragma unroll
    for (int i = tid; i < M_PER_BLOCK * OC / 4; i += THREADS) {
        int m_local = i >> 4;          // 16 float4 per m-row
        int o0      = (i & 15) * 4;    // first output channel of this float4
        float f0 = dens_s[m_local];
        float f1 = q_s[m_local];
        float4 v;
        v.x = fmaf(f0, Ws[(o0 + 0) * 2], fmaf(f1, Ws[(o0 + 0) * 2 + 1], bs[o0 + 0]));
        v.y = fmaf(f0, Ws[(o0 + 1) * 2], fmaf(f1, Ws[(o0 + 1) * 2 + 1], bs[o0 + 1]));
        v.z = fmaf(f0, Ws[(o0 + 2) * 2], fmaf(f1, Ws[(o0 + 2) * 2 + 1], bs[o0 + 2]));
        v.w = fmaf(f0, Ws[(o0 + 3) * 2], fmaf(f1, Ws[(o0 + 3) * 2 + 1], bs[o0 + 3]));
        ob[i] = v;
    }
}

extern "C" void kernel_launch(void* const* d_in, const int* in_sizes, int n_in,
                              void* d_out, int out_size)
{
    const float* x     = (const float*)d_in[0];
    const float* y     = (const float*)d_in[1];
    const float* t     = (const float*)d_in[2];
    const float* sigma = (const float*)d_in[3];
    const float* W     = (const float*)d_in[4];
    const float* bias  = (const float*)d_in[5];
    float* out = (float*)d_out;

    dim3 grid(N_OUT / M_PER_BLOCK, BATCH);   // 16 x 8 = 128 blocks, single wave
    conv_deepset_kernel<<<grid, THREADS>>>(x, y, t, sigma, W, bias, out);
}

// round 4
// speedup vs baseline: 2.1163x; 2.1163x over previous
#include <cuda_runtime.h>
#include <math.h>

#define N_IN        1024
#define N_OUT       4096
#define BATCH       8
#define OC          64
#define THREADS     256
#define M_PER_BLOCK 256

#define GRID        13
#define NCELL       (GRID * GRID)          // 169
#define CELL        (4.0f / GRID)          // 0.30769
#define INV_CELL    (GRID / 4.0f)          // 3.25
// natural-log cutoff: terms with exponent < -T are dropped.
// T=45 -> e^-45 ~ 3e-20; with the reference's +1e-8 denominator guard this is
// ~1e-8 absolute error worst case. Far below the 1e-3 rel_err gate.
#define CUTOFF_T    45.0f

__device__ __forceinline__ float ex2_approx(float x) {
    float r;
    asm("ex2.approx.ftz.f32 %0, %1;" : "=f"(r) : "f"(x));
    return r;
}

__device__ __forceinline__ int cell_of(float v) {
    int c = (int)((v + 2.0f) * INV_CELL);
    return min(GRID - 1, max(0, c));
}

__global__ __launch_bounds__(THREADS, 1)
void conv_deepset_kernel(const float* __restrict__ x,
                         const float* __restrict__ y,
                         const float* __restrict__ t,
                         const float* __restrict__ sigma,
                         const float* __restrict__ W,
                         const float* __restrict__ bias,
                         float* __restrict__ out)
{
    __shared__ float4 pts[N_IN];              // scaled (sx, sy, yval, pad), sorted by cell
    __shared__ int    cnt[NCELL];
    __shared__ int    start[NCELL + 1];
    __shared__ int    ofs[NCELL];
    __shared__ float  dens_s[M_PER_BLOCK];
    __shared__ float  q_s[M_PER_BLOCK];
    __shared__ float  Ws[2 * OC];
    __shared__ float  bs[OC];

    const int b   = blockIdx.y;
    const int tid = threadIdx.x;

    // ---- per-channel constants ----
    const float LOG2E = 1.4426950408889634f;
    const float s0 = expf(sigma[0]);
    const float s1 = expf(sigma[1]);
    // e_k = exp2( -d * uk^2 ),  uk^2 = 0.5*LOG2E/sk^2
    const float u0sq  = 0.5f * LOG2E / (s0 * s0);
    const float u0    = sqrtf(u0sq);
    const float ratio = (s0 * s0) / (s1 * s1);   // d1' = d0' * ratio
    const bool  equal_sig = (s0 == s1);

    // neighborhood half-width in cells, from the *larger* scale
    const float smax = fmaxf(s0, s1);
    const float r_needed = sqrtf(2.0f * CUTOFF_T) * smax;
    int nb = (int)ceilf(r_needed * INV_CELL);
    nb = max(1, min(GRID - 1, nb));

    // ---- phase 0: zero counts, stage W/b ----
    if (tid < NCELL) cnt[tid] = 0;
    if (tid < 2 * OC) Ws[tid] = W[tid];
    if (tid < OC)     bs[tid] = bias[tid];
    __syncthreads();

    // ---- phase 1: load 4 points/thread, count cells (coalesced loads) ----
    const float2* __restrict__ xb = (const float2*)(x + (size_t)b * N_IN * 2);
    const float*  __restrict__ yb = y + (size_t)b * N_IN;

    float2 pxv[4]; float pyv[4]; int pcell[4];
    #pragma unroll
    for (int k = 0; k < 4; ++k) {
        int i = tid + k * THREADS;
        float2 xv = xb[i];
        pxv[k] = xv;
        pyv[k] = yb[i];
        int c = cell_of(xv.y) * GRID + cell_of(xv.x);
        pcell[k] = c;
        atomicAdd(&cnt[c], 1);
    }
    __syncthreads();

    // ---- phase 2: exclusive scan over 169 cells (warp 0) ----
    if (tid < 32) {
        int lane = tid;
        int carry = 0;
        #pragma unroll
        for (int base = 0; base < NCELL + 31; base += 32) {
            int c = base + lane;
            int v = (c < NCELL) ? cnt[c] : 0;
            int s = v;
            #pragma unroll
            for (int off = 1; off < 32; off <<= 1) {
                int n = __shfl_up_sync(0xffffffffu, s, off);
                if (lane >= off) s += n;
            }
            int excl = s - v + carry;
            if (c < NCELL) { start[c] = excl; ofs[c] = excl; }
            carry += __shfl_sync(0xffffffffu, s, 31);
            if (base + 32 >= NCELL && lane == 0) start[NCELL] = carry;
        }
    }
    __syncthreads();

    // ---- phase 3: scatter scaled points into sorted order ----
    #pragma unroll
    for (int k = 0; k < 4; ++k) {
        int slot = atomicAdd(&ofs[pcell[k]], 1);
        pts[slot] = make_float4(pxv[k].x * u0, pxv[k].y * u0, pyv[k], 0.0f);
    }
    __syncthreads();

    // ---- phase 4: query — each thread handles one target point ----
    const int m = blockIdx.x * M_PER_BLOCK + tid;
    const float2 tv = ((const float2*)(t + (size_t)b * N_OUT * 2))[m];
    const float stx = tv.x * u0;
    const float sty = tv.y * u0;

    const int cx = cell_of(tv.x);
    const int cy = cell_of(tv.y);
    const int cx0 = max(0, cx - nb), cx1 = min(GRID - 1, cx + nb);
    const int cy0 = max(0, cy - nb), cy1 = min(GRID - 1, cy + nb);

    float acc0 = 0.0f;   // density channel
    float acc1 = 0.0f;   // conv channel

    if (equal_sig) {
        for (int ry = cy0; ry <= cy1; ++ry) {
            int js = start[ry * GRID + cx0];
            int je = start[ry * GRID + cx1 + 1];
            for (int j = js; j < je; ++j) {
                float4 p = pts[j];
                float dx = p.x - stx;
                float dy = p.y - sty;
                float d  = fmaf(dy, dy, dx * dx);
                float e0 = ex2_approx(-d);
                acc0 += e0;
                acc1 = fmaf(p.z, e0, acc1);
            }
        }
    } else {
        for (int ry = cy0; ry <= cy1; ++ry) {
            int js = start[ry * GRID + cx0];
            int je = start[ry * GRID + cx1 + 1];
            for (int j = js; j < je; ++j) {
                float4 p = pts[j];
                float dx = p.x - stx;
                float dy = p.y - sty;
                float d  = fmaf(dy, dy, dx * dx);
                float e0 = ex2_approx(-d);
                float e1 = ex2_approx(-d * ratio);
                acc0 += e0;
                acc1 = fmaf(p.z, e1, acc1);
            }
        }
    }

    dens_s[tid] = acc0;
    q_s[tid]    = acc1 / (acc0 + 1e-8f);
    __syncthreads();

    // ---- epilogue: out[b, m, o] = dens*W[o,0] + q*W[o,1] + b[o] ----
    float4* __restrict__ ob =
        (float4*)(out + ((size_t)b * N_OUT + (size_t)blockIdx.x * M_PER_BLOCK) * OC);

    #pragma unroll
    for (int i = tid; i < M_PER_BLOCK * OC / 4; i += THREADS) {
        int m_local = i >> 4;          // 16 float4 per m-row
        int o0      = (i & 15) * 4;
        float f0 = dens_s[m_local];
        float f1 = q_s[m_local];
        float4 v;
        v.x = fmaf(f0, Ws[(o0 + 0) * 2], fmaf(f1, Ws[(o0 + 0) * 2 + 1], bs[o0 + 0]));
        v.y = fmaf(f0, Ws[(o0 + 1) * 2], fmaf(f1, Ws[(o0 + 1) * 2 + 1], bs[o0 + 1]));
        v.z = fmaf(f0, Ws[(o0 + 2) * 2], fmaf(f1, Ws[(o0 + 2) * 2 + 1], bs[o0 + 2]));
        v.w = fmaf(f0, Ws[(o0 + 3) * 2], fmaf(f1, Ws[(o0 + 3) * 2 + 1], bs[o0 + 3]));
        ob[i] = v;
    }
}

extern "C" void kernel_launch(void* const* d_in, const int* in_sizes, int n_in,
                              void* d_out, int out_size)
{
    const float* x     = (const float*)d_in[0];
    const float* y     = (const float*)d_in[1];
    const float* t     = (const float*)d_in[2];
    const float* sigma = (const float*)d_in[3];
    const float* W     = (const float*)d_in[4];
    const float* bias  = (const float*)d_in[5];
    float* out = (float*)d_out;

    dim3 grid(N_OUT / M_PER_BLOCK, BATCH);   // 16 x 8 = 128 blocks, single wave
    conv_deepset_kernel<<<grid, THREADS>>>(x, y, t, sigma, W, bias, out);
}